// round 7
// baseline (speedup 1.0000x reference)
#include <cuda_runtime.h>

#define N_NODES 50000
#define N_EDGES 600000
#define F_MID 128
#define F_OUT 64

// ---------------- scratch (static __device__, 256B-aligned) ----------------
__device__ __align__(256) float g_h1[N_NODES * F_MID];   // x @ W1 ; reused for h2
__device__ __align__(256) float g_a1[N_NODES * F_MID];   // relu(agg1 + b1)
__device__ __align__(256) float g_h2[N_NODES * F_OUT];   // a1 @ W2
__device__ __align__(256) float g_dinv[N_NODES];
__device__ __align__(256) int   g_deg[N_NODES];
__device__ __align__(256) int   g_rowptr[N_NODES + 1];
__device__ __align__(256) int   g_pos[N_NODES];
__device__ __align__(256) int   g_esrc[N_EDGES];
__device__ int g_is64;   // 1 if edge_index is int64, 0 if int32

// ---------------- edge dtype detection -------------------------------------
// int64 values < 50000 look like [v,0,v,0,...] as int32 pairs. Check 128 odd
// positions; genuine int32 edge data (uniform in [0,50000)) is ~never all-zero
// at those positions.
__global__ void detect_dtype_kernel(const void* __restrict__ ei) {
    if (threadIdx.x == 0 && blockIdx.x == 0) {
        const int* p = (const int*)ei;
        int allz = 1;
        for (int i = 0; i < 128; i++)
            if (p[2 * i + 1] != 0) { allz = 0; break; }
        g_is64 = allz;
    }
}

__device__ __forceinline__ int load_edge(const void* ei, long long idx) {
    if (g_is64) return (int)((const long long*)ei)[idx];
    return ((const int*)ei)[idx];
}

// ---------------- CSR construction -----------------------------------------
__global__ void zero_deg_kernel() {
    int i = blockIdx.x * blockDim.x + threadIdx.x;
    if (i < N_NODES) g_deg[i] = 0;
}

__global__ void count_deg_kernel(const void* __restrict__ ei) {
    int e = blockIdx.x * blockDim.x + threadIdx.x;
    if (e < N_EDGES) {
        int d = load_edge(ei, (long long)N_EDGES + e);  // dst row
        if ((unsigned)d < (unsigned)N_NODES) atomicAdd(&g_deg[d], 1);
    }
}

// exclusive scan of g_deg -> g_rowptr, single block of 1024, warp-shfl based
__global__ void scan_deg_kernel() {
    __shared__ int warpsums[32];
    __shared__ int carry_s;
    int tid = threadIdx.x, lane = tid & 31, wid = tid >> 5;
    if (tid == 0) carry_s = 0;
    __syncthreads();
    for (int base = 0; base < N_NODES; base += 1024) {
        int i = base + tid;
        int v = (i < N_NODES) ? g_deg[i] : 0;
        int s = v;
        #pragma unroll
        for (int off = 1; off < 32; off <<= 1) {
            int t = __shfl_up_sync(0xffffffffu, s, off);
            if (lane >= off) s += t;
        }
        if (lane == 31) warpsums[wid] = s;
        __syncthreads();
        if (wid == 0) {
            int w = warpsums[lane];
            int sw = w;
            #pragma unroll
            for (int off = 1; off < 32; off <<= 1) {
                int t = __shfl_up_sync(0xffffffffu, sw, off);
                if (lane >= off) sw += t;
            }
            warpsums[lane] = sw - w;  // exclusive warp offsets
        }
        __syncthreads();
        int incl = s + warpsums[wid];
        int excl = incl - v;
        int c = carry_s;
        if (i < N_NODES) g_rowptr[i] = c + excl;
        __syncthreads();
        if (tid == 1023) carry_s = c + incl;  // incl at tid 1023 == chunk total
        __syncthreads();
    }
    if (threadIdx.x == 0) g_rowptr[N_NODES] = carry_s;
}

__global__ void prep_kernel() {
    int i = blockIdx.x * blockDim.x + threadIdx.x;
    if (i < N_NODES) {
        g_pos[i] = g_rowptr[i];
        // reference degree = in-degree (by dst) + 1 self-loop; always > 0
        g_dinv[i] = rsqrtf((float)(g_deg[i] + 1));
    }
}

__global__ void fill_csr_kernel(const void* __restrict__ ei) {
    int e = blockIdx.x * blockDim.x + threadIdx.x;
    if (e < N_EDGES) {
        int s = load_edge(ei, e);
        int d = load_edge(ei, (long long)N_EDGES + e);
        if ((unsigned)d < (unsigned)N_NODES && (unsigned)s < (unsigned)N_NODES) {
            int idx = atomicAdd(&g_pos[d], 1);
            g_esrc[idx] = s;
        }
    }
}

// ---------------- fp32 SGEMM layer 1: g_h1[M,128] = x[M,128] * W1[128,128] --
// BM=128, BK=8, 8x8 microtile, 256 threads.
__global__ void gemm1_kernel(const float* __restrict__ A,
                             const float* __restrict__ B) {
    constexpr int BM = 128, BN = 128, BK = 8;
    constexpr int TX = BN / 8;        // 16
    constexpr int T  = TX * 16;       // 256
    const int M = N_NODES;

    __shared__ float As[BK][BM];
    __shared__ float Bs[BK][BN];

    int tid = threadIdx.x;
    int tx = tid % TX;
    int ty = tid / TX;
    int row0 = blockIdx.x * BM;

    float acc[8][8];
    #pragma unroll
    for (int i = 0; i < 8; i++)
        #pragma unroll
        for (int j = 0; j < 8; j++) acc[i][j] = 0.f;

    for (int kb = 0; kb < 128; kb += BK) {
        for (int i = tid; i < BM * BK; i += T) {
            int r = i / BK, c = i % BK;
            int gr = row0 + r;
            As[c][r] = (gr < M) ? A[gr * 128 + kb + c] : 0.f;
        }
        for (int i = tid; i < BK * BN; i += T) {
            int r = i / BN, c = i % BN;
            Bs[r][c] = B[(kb + r) * BN + c];
        }
        __syncthreads();
        #pragma unroll
        for (int kk = 0; kk < BK; kk++) {
            float a[8], b[8];
            #pragma unroll
            for (int i = 0; i < 8; i++) a[i] = As[kk][ty * 8 + i];
            #pragma unroll
            for (int j = 0; j < 8; j++) b[j] = Bs[kk][tx * 8 + j];
            #pragma unroll
            for (int i = 0; i < 8; i++)
                #pragma unroll
                for (int j = 0; j < 8; j++)
                    acc[i][j] = fmaf(a[i], b[j], acc[i][j]);
        }
        __syncthreads();
    }

    #pragma unroll
    for (int i = 0; i < 8; i++) {
        int gr = row0 + ty * 8 + i;
        if (gr < M) {
            float* cp = &g_h1[gr * BN + tx * 8];
            #pragma unroll
            for (int j = 0; j < 8; j++) cp[j] = acc[i][j];
        }
    }
}

// ---------------- fp32 SGEMM layer 2: g_h2[M,64] = g_a1[M,128] * W2[128,64] -
__global__ void gemm2_kernel(const float* __restrict__ B) {
    constexpr int BM = 128, BN = 64, BK = 8;
    constexpr int TX = BN / 8;        // 8
    constexpr int T  = TX * 16;       // 128
    const int M = N_NODES;

    __shared__ float As[BK][BM];
    __shared__ float Bs[BK][BN];

    int tid = threadIdx.x;
    int tx = tid % TX;
    int ty = tid / TX;
    int row0 = blockIdx.x * BM;

    float acc[8][8];
    #pragma unroll
    for (int i = 0; i < 8; i++)
        #pragma unroll
        for (int j = 0; j < 8; j++) acc[i][j] = 0.f;

    for (int kb = 0; kb < 128; kb += BK) {
        for (int i = tid; i < BM * BK; i += T) {
            int r = i / BK, c = i % BK;
            int gr = row0 + r;
            As[c][r] = (gr < M) ? g_a1[gr * 128 + kb + c] : 0.f;
        }
        for (int i = tid; i < BK * BN; i += T) {
            int r = i / BN, c = i % BN;
            Bs[r][c] = B[(kb + r) * BN + c];
        }
        __syncthreads();
        #pragma unroll
        for (int kk = 0; kk < BK; kk++) {
            float a[8], b[8];
            #pragma unroll
            for (int i = 0; i < 8; i++) a[i] = As[kk][ty * 8 + i];
            #pragma unroll
            for (int j = 0; j < 8; j++) b[j] = Bs[kk][tx * 8 + j];
            #pragma unroll
            for (int i = 0; i < 8; i++)
                #pragma unroll
                for (int j = 0; j < 8; j++)
                    acc[i][j] = fmaf(a[i], b[j], acc[i][j]);
        }
        __syncthreads();
    }

    #pragma unroll
    for (int i = 0; i < 8; i++) {
        int gr = row0 + ty * 8 + i;
        if (gr < M) {
            float* cp = &g_h2[gr * BN + tx * 8];
            #pragma unroll
            for (int j = 0; j < 8; j++) cp[j] = acc[i][j];
        }
    }
}

// ---------------- aggregation: warp-per-node gather ------------------------
// g_a1[i] = relu( dinv[i]^2*h1[i] + sum_e dinv[src]*dinv[i]*h1[src] + b1 )
__global__ void agg_relu_bias_128_kernel(const float* __restrict__ bias) {
    int gw = (blockIdx.x * blockDim.x + threadIdx.x) >> 5;
    int lane = threadIdx.x & 31;
    if (gw >= N_NODES) return;
    int node = gw;
    float di = g_dinv[node];
    const float4* hv = (const float4*)g_h1;
    float4 a = hv[node * 32 + lane];
    float w0 = di * di;
    float4 acc = make_float4(w0 * a.x, w0 * a.y, w0 * a.z, w0 * a.w);
    int e0 = g_rowptr[node], e1 = g_rowptr[node + 1];
    for (int e = e0; e < e1; e++) {
        int s = g_esrc[e];
        float w = di * g_dinv[s];
        float4 v = hv[s * 32 + lane];
        acc.x = fmaf(w, v.x, acc.x);
        acc.y = fmaf(w, v.y, acc.y);
        acc.z = fmaf(w, v.z, acc.z);
        acc.w = fmaf(w, v.w, acc.w);
    }
    float bx = bias[lane * 4 + 0], by = bias[lane * 4 + 1];
    float bz = bias[lane * 4 + 2], bw = bias[lane * 4 + 3];
    acc.x = fmaxf(acc.x + bx, 0.f);
    acc.y = fmaxf(acc.y + by, 0.f);
    acc.z = fmaxf(acc.z + bz, 0.f);
    acc.w = fmaxf(acc.w + bw, 0.f);
    ((float4*)g_a1)[node * 32 + lane] = acc;
}

// F=64 variant: float2 per lane, + bias, NO relu (final layer), writes d_out
__global__ void agg_bias_64_kernel(const float* __restrict__ bias,
                                   float* __restrict__ out) {
    int gw = (blockIdx.x * blockDim.x + threadIdx.x) >> 5;
    int lane = threadIdx.x & 31;
    if (gw >= N_NODES) return;
    int node = gw;
    float di = g_dinv[node];
    const float2* hv = (const float2*)g_h2;
    float2 a = hv[node * 32 + lane];
    float w0 = di * di;
    float2 acc = make_float2(w0 * a.x, w0 * a.y);
    int e0 = g_rowptr[node], e1 = g_rowptr[node + 1];
    for (int e = e0; e < e1; e++) {
        int s = g_esrc[e];
        float w = di * g_dinv[s];
        float2 v = hv[s * 32 + lane];
        acc.x = fmaf(w, v.x, acc.x);
        acc.y = fmaf(w, v.y, acc.y);
    }
    acc.x += bias[lane * 2 + 0];
    acc.y += bias[lane * 2 + 1];
    out[node * 64 + lane * 2 + 0] = acc.x;
    out[node * 64 + lane * 2 + 1] = acc.y;
}

// ---------------- launch ----------------------------------------------------
extern "C" void kernel_launch(void* const* d_in, const int* in_sizes, int n_in,
                              void* d_out, int out_size) {
    const float* x  = (const float*)d_in[0];
    const void*  ei = d_in[1];                 // int32 or int64 — sniffed on device
    const float* W1 = (const float*)d_in[2];
    const float* b1 = (const float*)d_in[3];
    const float* W2 = (const float*)d_in[4];
    const float* b2 = (const float*)d_in[5];
    float* out = (float*)d_out;

    // edge dtype detection + CSR-by-dst build (deterministic each call)
    detect_dtype_kernel<<<1, 32>>>(ei);
    zero_deg_kernel<<<(N_NODES + 255) / 256, 256>>>();
    count_deg_kernel<<<(N_EDGES + 255) / 256, 256>>>(ei);
    scan_deg_kernel<<<1, 1024>>>();
    prep_kernel<<<(N_NODES + 255) / 256, 256>>>();
    fill_csr_kernel<<<(N_EDGES + 255) / 256, 256>>>(ei);

    // layer 1: h1 = x@W1 ; a1 = relu(agg(h1) + b1)
    gemm1_kernel<<<(N_NODES + 127) / 128, 256>>>(x, W1);
    agg_relu_bias_128_kernel<<<(N_NODES * 32 + 255) / 256, 256>>>(b1);

    // layer 2: h2 = a1@W2 ; out = agg(h2) + b2
    gemm2_kernel<<<(N_NODES + 127) / 128, 128>>>(W2);
    agg_bias_64_kernel<<<(N_NODES * 32 + 255) / 256, 256>>>(b2, out);
}

// round 9
// speedup vs baseline: 1.1915x; 1.1915x over previous
#include <cuda_runtime.h>

#define N_NODES 50000
#define N_EDGES 600000
#define F_MID 128
#define F_OUT 64
#define SCAN_BLOCKS ((N_NODES + 1023) / 1024)   // 49

// ---------------- scratch (static __device__, 256B-aligned) ----------------
__device__ __align__(256) float g_h1[N_NODES * F_MID];   // x @ W1
__device__ __align__(256) float g_a1[N_NODES * F_MID];   // relu(agg1 + b1)
__device__ __align__(256) float g_h2[N_NODES * F_OUT];   // a1 @ W2
__device__ __align__(256) float g_dinv[N_NODES];
__device__ __align__(256) int   g_deg[N_NODES];
__device__ __align__(256) int   g_rowptr[N_NODES + 1];
__device__ __align__(256) int   g_pos[N_NODES];
__device__ __align__(256) int   g_esrc[N_EDGES];
__device__ __align__(256) int   g_blocksum[64];
__device__ __align__(256) int   g_blockoff[64];
__device__ int g_is64;   // 1 if edge_index is int64, 0 if int32

// ---------------- edge dtype detection -------------------------------------
__global__ void detect_dtype_kernel(const void* __restrict__ ei) {
    if (threadIdx.x == 0 && blockIdx.x == 0) {
        const int* p = (const int*)ei;
        int allz = 1;
        for (int i = 0; i < 128; i++)
            if (p[2 * i + 1] != 0) { allz = 0; break; }
        g_is64 = allz;
    }
}

__device__ __forceinline__ int load_edge(const void* ei, long long idx) {
    if (g_is64) return (int)((const long long*)ei)[idx];
    return ((const int*)ei)[idx];
}

// ---------------- CSR construction -----------------------------------------
__global__ void zero_deg_kernel() {
    int i = blockIdx.x * blockDim.x + threadIdx.x;
    if (i < N_NODES) g_deg[i] = 0;
}

__global__ void count_deg_kernel(const void* __restrict__ ei) {
    int e = blockIdx.x * blockDim.x + threadIdx.x;
    if (e < N_EDGES) {
        int d = load_edge(ei, (long long)N_EDGES + e);  // dst row
        if ((unsigned)d < (unsigned)N_NODES) atomicAdd(&g_deg[d], 1);
    }
}

// Phase 1: per-block (1024-wide) local exclusive scan + block totals
__global__ void scan_local_kernel() {
    __shared__ int warpsums[32];
    int tid = threadIdx.x, lane = tid & 31, wid = tid >> 5;
    int i = blockIdx.x * 1024 + tid;
    int v = (i < N_NODES) ? g_deg[i] : 0;
    int s = v;
    #pragma unroll
    for (int off = 1; off < 32; off <<= 1) {
        int t = __shfl_up_sync(0xffffffffu, s, off);
        if (lane >= off) s += t;
    }
    if (lane == 31) warpsums[wid] = s;
    __syncthreads();
    if (wid == 0) {
        int w = warpsums[lane];
        int sw = w;
        #pragma unroll
        for (int off = 1; off < 32; off <<= 1) {
            int t = __shfl_up_sync(0xffffffffu, sw, off);
            if (lane >= off) sw += t;
        }
        warpsums[lane] = sw - w;   // exclusive warp offsets
    }
    __syncthreads();
    int incl = s + warpsums[wid];
    if (i < N_NODES) g_rowptr[i] = incl - v;     // block-local exclusive
    if (tid == 1023) g_blocksum[blockIdx.x] = incl;
}

// Phase 2: exclusive scan of the <=64 block sums (2 warps)
__global__ void scan_sums_kernel() {
    __shared__ int w0tot;
    int t = threadIdx.x, lane = t & 31, wid = t >> 5;
    int v = (t < SCAN_BLOCKS) ? g_blocksum[t] : 0;
    int s = v;
    #pragma unroll
    for (int off = 1; off < 32; off <<= 1) {
        int u = __shfl_up_sync(0xffffffffu, s, off);
        if (lane >= off) s += u;
    }
    if (wid == 0 && lane == 31) w0tot = s;
    __syncthreads();
    int incl = s + (wid == 1 ? w0tot : 0);
    if (t < 64) g_blockoff[t] = incl - v;
    if (t == 63) g_rowptr[N_NODES] = incl;       // total (== N_EDGES normally)
}

// Phase 3: add block offsets; fused prep (pos, dinv)
__global__ void scan_finalize_kernel() {
    int i = blockIdx.x * blockDim.x + threadIdx.x;
    if (i < N_NODES) {
        int r = g_rowptr[i] + g_blockoff[i >> 10];
        g_rowptr[i] = r;
        g_pos[i] = r;
        g_dinv[i] = rsqrtf((float)(g_deg[i] + 1));  // +1 self-loop; always > 0
    }
}

__global__ void fill_csr_kernel(const void* __restrict__ ei) {
    int e = blockIdx.x * blockDim.x + threadIdx.x;
    if (e < N_EDGES) {
        int s = load_edge(ei, e);
        int d = load_edge(ei, (long long)N_EDGES + e);
        if ((unsigned)d < (unsigned)N_NODES && (unsigned)s < (unsigned)N_NODES) {
            int idx = atomicAdd(&g_pos[d], 1);
            g_esrc[idx] = s;
        }
    }
}

// ---------------- double-buffered fp32 SGEMM -------------------------------
// C[M,BN] = A[M,128] * B[128,BN].  BM=128, BK=16, 8x8 microtile.
// LAYER1: A = x (param), C = g_h1.  else: A = g_a1, C = g_h2.
template <int BN, bool LAYER1>
__global__ void gemm_db_kernel(const float* __restrict__ Ain,
                               const float* __restrict__ B) {
    constexpr int BM = 128, BK = 16;
    constexpr int TX = BN / 8;          // 16 or 8
    constexpr int T  = 2 * BN;          // 256 or 128 threads
    constexpr int NA = (BM * BK / 4) / T;  // float4 A loads per thread: 2 or 4
    constexpr int NB = (BK * BN / 4) / T;  // float4 B loads per thread: 2 or 2
    const int M = N_NODES;
    const float* A = LAYER1 ? Ain : (const float*)g_a1;

    __shared__ float As[2][BK][BM];
    __shared__ float Bs[2][BK][BN];

    int tid = threadIdx.x;
    int tx = tid % TX;
    int ty = tid / TX;                  // [0,16)
    int row0 = blockIdx.x * BM;

    float acc[8][8];
    #pragma unroll
    for (int i = 0; i < 8; i++)
        #pragma unroll
        for (int j = 0; j < 8; j++) acc[i][j] = 0.f;

    float4 ra[NA], rb[NB];

    // fetch stage (global -> regs)
    auto fetch = [&](int kb) {
        #pragma unroll
        for (int k = 0; k < NA; k++) {
            int idx = tid + k * T;            // [0, 512)
            int ar = idx >> 2, ac4 = idx & 3; // row in tile, float4-col
            int gr = row0 + ar;
            ra[k] = (gr < M) ? *(const float4*)&A[gr * 128 + kb + ac4 * 4]
                             : make_float4(0.f, 0.f, 0.f, 0.f);
        }
        #pragma unroll
        for (int k = 0; k < NB; k++) {
            int idx = tid + k * T;                        // [0, 4*BN)
            int br = idx / (BN / 4), bc4 = idx % (BN / 4);
            rb[k] = *(const float4*)&B[(br + kb) * BN + bc4 * 4];
        }
    };
    // commit stage (regs -> smem)
    auto commit = [&](int buf) {
        #pragma unroll
        for (int k = 0; k < NA; k++) {
            int idx = tid + k * T;
            int ar = idx >> 2, ac4 = idx & 3;
            As[buf][ac4 * 4 + 0][ar] = ra[k].x;
            As[buf][ac4 * 4 + 1][ar] = ra[k].y;
            As[buf][ac4 * 4 + 2][ar] = ra[k].z;
            As[buf][ac4 * 4 + 3][ar] = ra[k].w;
        }
        #pragma unroll
        for (int k = 0; k < NB; k++) {
            int idx = tid + k * T;
            int br = idx / (BN / 4), bc4 = idx % (BN / 4);
            *(float4*)&Bs[buf][br][bc4 * 4] = rb[k];
        }
    };

    fetch(0);
    commit(0);
    __syncthreads();

    #pragma unroll
    for (int t = 0; t < 128 / BK; t++) {
        int cur = t & 1;
        if (t < 128 / BK - 1) fetch((t + 1) * BK);   // loads in flight over compute
        #pragma unroll
        for (int kk = 0; kk < BK; kk++) {
            float a[8], b[8];
            #pragma unroll
            for (int i = 0; i < 8; i++) a[i] = As[cur][kk][ty * 8 + i];
            #pragma unroll
            for (int j = 0; j < 8; j++) b[j] = Bs[cur][kk][tx * 8 + j];
            #pragma unroll
            for (int i = 0; i < 8; i++)
                #pragma unroll
                for (int j = 0; j < 8; j++)
                    acc[i][j] = fmaf(a[i], b[j], acc[i][j]);
        }
        if (t < 128 / BK - 1) commit(cur ^ 1);
        __syncthreads();
    }

    float* C = LAYER1 ? (float*)g_h1 : (float*)g_h2;
    #pragma unroll
    for (int i = 0; i < 8; i++) {
        int gr = row0 + ty * 8 + i;
        if (gr < M) {
            float4* cp = (float4*)&C[gr * BN + tx * 8];
            cp[0] = make_float4(acc[i][0], acc[i][1], acc[i][2], acc[i][3]);
            cp[1] = make_float4(acc[i][4], acc[i][5], acc[i][6], acc[i][7]);
        }
    }
}

// ---------------- aggregation: warp-per-node gather ------------------------
// g_a1[i] = relu( dinv[i]^2*h1[i] + sum_e dinv[src]*dinv[i]*h1[src] + b1 )
__global__ void agg_relu_bias_128_kernel(const float* __restrict__ bias) {
    int gw = (blockIdx.x * blockDim.x + threadIdx.x) >> 5;
    int lane = threadIdx.x & 31;
    if (gw >= N_NODES) return;
    int node = gw;
    float di = g_dinv[node];
    const float4* hv = (const float4*)g_h1;
    float4 a = hv[node * 32 + lane];
    float w0 = di * di;
    float4 acc = make_float4(w0 * a.x, w0 * a.y, w0 * a.z, w0 * a.w);
    int e0 = g_rowptr[node], e1 = g_rowptr[node + 1];
    for (int e = e0; e < e1; e++) {
        int s = g_esrc[e];
        float w = di * g_dinv[s];
        float4 v = hv[s * 32 + lane];
        acc.x = fmaf(w, v.x, acc.x);
        acc.y = fmaf(w, v.y, acc.y);
        acc.z = fmaf(w, v.z, acc.z);
        acc.w = fmaf(w, v.w, acc.w);
    }
    float bx = bias[lane * 4 + 0], by = bias[lane * 4 + 1];
    float bz = bias[lane * 4 + 2], bw = bias[lane * 4 + 3];
    acc.x = fmaxf(acc.x + bx, 0.f);
    acc.y = fmaxf(acc.y + by, 0.f);
    acc.z = fmaxf(acc.z + bz, 0.f);
    acc.w = fmaxf(acc.w + bw, 0.f);
    ((float4*)g_a1)[node * 32 + lane] = acc;
}

// F=64 variant: float2 per lane, + bias, NO relu (final layer), writes d_out
__global__ void agg_bias_64_kernel(const float* __restrict__ bias,
                                   float* __restrict__ out) {
    int gw = (blockIdx.x * blockDim.x + threadIdx.x) >> 5;
    int lane = threadIdx.x & 31;
    if (gw >= N_NODES) return;
    int node = gw;
    float di = g_dinv[node];
    const float2* hv = (const float2*)g_h2;
    float2 a = hv[node * 32 + lane];
    float w0 = di * di;
    float2 acc = make_float2(w0 * a.x, w0 * a.y);
    int e0 = g_rowptr[node], e1 = g_rowptr[node + 1];
    for (int e = e0; e < e1; e++) {
        int s = g_esrc[e];
        float w = di * g_dinv[s];
        float2 v = hv[s * 32 + lane];
        acc.x = fmaf(w, v.x, acc.x);
        acc.y = fmaf(w, v.y, acc.y);
    }
    acc.x += bias[lane * 2 + 0];
    acc.y += bias[lane * 2 + 1];
    out[node * 64 + lane * 2 + 0] = acc.x;
    out[node * 64 + lane * 2 + 1] = acc.y;
}

// ---------------- launch ----------------------------------------------------
extern "C" void kernel_launch(void* const* d_in, const int* in_sizes, int n_in,
                              void* d_out, int out_size) {
    const float* x  = (const float*)d_in[0];
    const void*  ei = d_in[1];                 // int32 or int64 — sniffed on device
    const float* W1 = (const float*)d_in[2];
    const float* b1 = (const float*)d_in[3];
    const float* W2 = (const float*)d_in[4];
    const float* b2 = (const float*)d_in[5];
    float* out = (float*)d_out;

    // edge dtype detection + CSR-by-dst build (deterministic each call)
    detect_dtype_kernel<<<1, 32>>>(ei);
    zero_deg_kernel<<<(N_NODES + 255) / 256, 256>>>();
    count_deg_kernel<<<(N_EDGES + 255) / 256, 256>>>(ei);
    scan_local_kernel<<<SCAN_BLOCKS, 1024>>>();
    scan_sums_kernel<<<1, 64>>>();
    scan_finalize_kernel<<<(N_NODES + 255) / 256, 256>>>();
    fill_csr_kernel<<<(N_EDGES + 255) / 256, 256>>>(ei);

    // layer 1: h1 = x@W1 ; a1 = relu(agg(h1) + b1)
    gemm_db_kernel<128, true><<<(N_NODES + 127) / 128, 256>>>(x, W1);
    agg_relu_bias_128_kernel<<<(N_NODES * 32 + 255) / 256, 256>>>(b1);

    // layer 2: h2 = a1@W2 ; out = agg(h2) + b2
    gemm_db_kernel<64, false><<<(N_NODES + 127) / 128, 128>>>(nullptr, W2);
    agg_bias_64_kernel<<<(N_NODES * 32 + 255) / 256, 256>>>(b2, out);
}

// round 10
// speedup vs baseline: 1.7905x; 1.5027x over previous
#include <cuda_runtime.h>
#include <cstdint>

#define N_NODES 50000
#define N_EDGES 600000
#define F_MID 128
#define F_OUT 64
#define SCAN_BLOCKS ((N_NODES + 1023) / 1024)   // 49

// ---------------- scratch (static __device__, 256B-aligned) ----------------
__device__ __align__(256) float g_h1[N_NODES * F_MID];   // x @ W1
__device__ __align__(256) float g_a1[N_NODES * F_MID];   // relu(agg1 + b1)
__device__ __align__(256) float g_h2[N_NODES * F_OUT];   // a1 @ W2
__device__ __align__(256) float g_dinv[N_NODES];
__device__ __align__(256) int   g_deg[N_NODES];
__device__ __align__(256) int   g_rowptr[N_NODES + 1];
__device__ __align__(256) int   g_pos[N_NODES];
__device__ __align__(256) int   g_esrc[N_EDGES];
__device__ __align__(256) int   g_blocksum[64];
__device__ __align__(256) int   g_blockoff[64];
__device__ int g_is64;   // 1 if edge_index is int64, 0 if int32

// ---------------- edge dtype detection -------------------------------------
__global__ void detect_dtype_kernel(const void* __restrict__ ei) {
    if (threadIdx.x == 0 && blockIdx.x == 0) {
        const int* p = (const int*)ei;
        int allz = 1;
        for (int i = 0; i < 128; i++)
            if (p[2 * i + 1] != 0) { allz = 0; break; }
        g_is64 = allz;
    }
}

__device__ __forceinline__ int load_edge(const void* ei, long long idx) {
    if (g_is64) return (int)((const long long*)ei)[idx];
    return ((const int*)ei)[idx];
}

// ---------------- CSR construction -----------------------------------------
__global__ void zero_deg_kernel() {
    int i = blockIdx.x * blockDim.x + threadIdx.x;
    if (i < N_NODES) g_deg[i] = 0;
}

__global__ void count_deg_kernel(const void* __restrict__ ei) {
    int e = blockIdx.x * blockDim.x + threadIdx.x;
    if (e < N_EDGES) {
        int d = load_edge(ei, (long long)N_EDGES + e);  // dst row
        if ((unsigned)d < (unsigned)N_NODES) atomicAdd(&g_deg[d], 1);
    }
}

// Phase 1: per-block (1024-wide) local exclusive scan + block totals
__global__ void scan_local_kernel() {
    __shared__ int warpsums[32];
    int tid = threadIdx.x, lane = tid & 31, wid = tid >> 5;
    int i = blockIdx.x * 1024 + tid;
    int v = (i < N_NODES) ? g_deg[i] : 0;
    int s = v;
    #pragma unroll
    for (int off = 1; off < 32; off <<= 1) {
        int t = __shfl_up_sync(0xffffffffu, s, off);
        if (lane >= off) s += t;
    }
    if (lane == 31) warpsums[wid] = s;
    __syncthreads();
    if (wid == 0) {
        int w = warpsums[lane];
        int sw = w;
        #pragma unroll
        for (int off = 1; off < 32; off <<= 1) {
            int t = __shfl_up_sync(0xffffffffu, sw, off);
            if (lane >= off) sw += t;
        }
        warpsums[lane] = sw - w;   // exclusive warp offsets
    }
    __syncthreads();
    int incl = s + warpsums[wid];
    if (i < N_NODES) g_rowptr[i] = incl - v;     // block-local exclusive
    if (tid == 1023) g_blocksum[blockIdx.x] = incl;
}

// Phase 2: exclusive scan of the <=64 block sums (2 warps)
__global__ void scan_sums_kernel() {
    __shared__ int w0tot;
    int t = threadIdx.x, lane = t & 31, wid = t >> 5;
    int v = (t < SCAN_BLOCKS) ? g_blocksum[t] : 0;
    int s = v;
    #pragma unroll
    for (int off = 1; off < 32; off <<= 1) {
        int u = __shfl_up_sync(0xffffffffu, s, off);
        if (lane >= off) s += u;
    }
    if (wid == 0 && lane == 31) w0tot = s;
    __syncthreads();
    int incl = s + (wid == 1 ? w0tot : 0);
    if (t < 64) g_blockoff[t] = incl - v;
    if (t == 63) g_rowptr[N_NODES] = incl;       // total (== N_EDGES normally)
}

// Phase 3: add block offsets; fused prep (pos, dinv)
__global__ void scan_finalize_kernel() {
    int i = blockIdx.x * blockDim.x + threadIdx.x;
    if (i < N_NODES) {
        int r = g_rowptr[i] + g_blockoff[i >> 10];
        g_rowptr[i] = r;
        g_pos[i] = r;
        g_dinv[i] = rsqrtf((float)(g_deg[i] + 1));  // +1 self-loop; always > 0
    }
}

__global__ void fill_csr_kernel(const void* __restrict__ ei) {
    int e = blockIdx.x * blockDim.x + threadIdx.x;
    if (e < N_EDGES) {
        int s = load_edge(ei, e);
        int d = load_edge(ei, (long long)N_EDGES + e);
        if ((unsigned)d < (unsigned)N_NODES && (unsigned)s < (unsigned)N_NODES) {
            int idx = atomicAdd(&g_pos[d], 1);
            g_esrc[idx] = s;
        }
    }
}

// ---------------- tf32 tensor-core GEMM ------------------------------------
// C[M,BN] = A[M,128] * B[128,BN], fp32 in/out, tf32 mma.sync m16n8k8.
// BM=128, BK=32, 256 threads = 8 warps in 2(m) x 4(n); warp tile 64 x (BN/4).
__device__ __forceinline__ uint32_t f2tf32(float f) {
    uint32_t u;
    asm("cvt.rna.tf32.f32 %0, %1;" : "=r"(u) : "f"(f));
    return u;
}

template <int BN, bool LAYER1>
__global__ void gemm_tc_kernel(const float* __restrict__ Ain,
                               const float* __restrict__ B) {
    constexpr int BM = 128, BK = 32;
    constexpr int MT = 4;                 // 64 rows / 16
    constexpr int NT = (BN / 4) / 8;      // 4 (BN=128) or 2 (BN=64)
    constexpr int NAv = 4;                // A float4 loads/thread (4096/4/256)
    constexpr int NBv = BN / 32;          // B float4 loads/thread (32*BN/4/256)
    const int M = N_NODES;
    const float* A = LAYER1 ? Ain : (const float*)g_a1;
    float* C = LAYER1 ? (float*)g_h1 : (float*)g_h2;

    __shared__ float As[BM][BK + 4];      // +4 pad: conflict-free frag reads
    __shared__ float Bs[BK][BN + 4];

    int tid = threadIdx.x;
    int lane = tid & 31;
    int w = tid >> 5;
    int warp_m = w >> 2, warp_n = w & 3;
    int mrow0 = warp_m * 64;
    int ncol0 = warp_n * (BN / 4);
    int g = lane >> 2, q = lane & 3;
    int row0 = blockIdx.x * BM;

    float acc[MT][NT][4];
    #pragma unroll
    for (int i = 0; i < MT; i++)
        #pragma unroll
        for (int j = 0; j < NT; j++)
            #pragma unroll
            for (int k = 0; k < 4; k++) acc[i][j][k] = 0.f;

    float4 ra[NAv], rb[NBv];
    auto fetch = [&](int kb) {
        #pragma unroll
        for (int k = 0; k < NAv; k++) {
            int idx = tid + k * 256;          // [0,1024) float4s
            int ar = idx >> 3, ac4 = idx & 7; // row, float4-col in 32-wide K
            int gr = row0 + ar;
            ra[k] = (gr < M) ? *(const float4*)&A[gr * 128 + kb + ac4 * 4]
                             : make_float4(0.f, 0.f, 0.f, 0.f);
        }
        #pragma unroll
        for (int k = 0; k < NBv; k++) {
            int idx = tid + k * 256;                      // [0, 8*BN)
            int br = idx / (BN / 4), bc4 = idx % (BN / 4);
            rb[k] = *(const float4*)&B[(kb + br) * BN + bc4 * 4];
        }
    };
    auto commit = [&]() {
        #pragma unroll
        for (int k = 0; k < NAv; k++) {
            int idx = tid + k * 256;
            int ar = idx >> 3, ac4 = idx & 7;
            *(float4*)&As[ar][ac4 * 4] = ra[k];
        }
        #pragma unroll
        for (int k = 0; k < NBv; k++) {
            int idx = tid + k * 256;
            int br = idx / (BN / 4), bc4 = idx % (BN / 4);
            *(float4*)&Bs[br][bc4 * 4] = rb[k];
        }
    };

    fetch(0);
    #pragma unroll
    for (int t = 0; t < 128 / BK; t++) {
        commit();
        __syncthreads();
        if (t < 128 / BK - 1) fetch((t + 1) * BK);   // next tile in flight
        #pragma unroll
        for (int ks = 0; ks < BK / 8; ks++) {
            int k0 = ks * 8;
            uint32_t af[MT][4];
            #pragma unroll
            for (int mt = 0; mt < MT; mt++) {
                int r = mrow0 + mt * 16 + g;
                af[mt][0] = f2tf32(As[r][k0 + q]);
                af[mt][1] = f2tf32(As[r + 8][k0 + q]);
                af[mt][2] = f2tf32(As[r][k0 + q + 4]);
                af[mt][3] = f2tf32(As[r + 8][k0 + q + 4]);
            }
            uint32_t bf[NT][2];
            #pragma unroll
            for (int nt = 0; nt < NT; nt++) {
                int c = ncol0 + nt * 8 + g;
                bf[nt][0] = f2tf32(Bs[k0 + q][c]);
                bf[nt][1] = f2tf32(Bs[k0 + q + 4][c]);
            }
            #pragma unroll
            for (int mt = 0; mt < MT; mt++)
                #pragma unroll
                for (int nt = 0; nt < NT; nt++) {
                    asm volatile(
                        "mma.sync.aligned.m16n8k8.row.col.f32.tf32.tf32.f32 "
                        "{%0,%1,%2,%3}, {%4,%5,%6,%7}, {%8,%9}, {%0,%1,%2,%3};"
                        : "+f"(acc[mt][nt][0]), "+f"(acc[mt][nt][1]),
                          "+f"(acc[mt][nt][2]), "+f"(acc[mt][nt][3])
                        : "r"(af[mt][0]), "r"(af[mt][1]),
                          "r"(af[mt][2]), "r"(af[mt][3]),
                          "r"(bf[nt][0]), "r"(bf[nt][1]));
                }
        }
        __syncthreads();
    }

    // epilogue: c0,c1 -> row g, cols 2q,2q+1 ; c2,c3 -> row g+8
    #pragma unroll
    for (int mt = 0; mt < MT; mt++) {
        int r = mrow0 + mt * 16 + g;
        int gr0 = row0 + r, gr1 = gr0 + 8;
        #pragma unroll
        for (int nt = 0; nt < NT; nt++) {
            int c = ncol0 + nt * 8 + 2 * q;
            if (gr0 < M)
                *(float2*)&C[gr0 * BN + c] = make_float2(acc[mt][nt][0], acc[mt][nt][1]);
            if (gr1 < M)
                *(float2*)&C[gr1 * BN + c] = make_float2(acc[mt][nt][2], acc[mt][nt][3]);
        }
    }
}

// ---------------- aggregation: warp-per-node gather ------------------------
// g_a1[i] = relu( dinv[i]^2*h1[i] + sum_e dinv[src]*dinv[i]*h1[src] + b1 )
__global__ void agg_relu_bias_128_kernel(const float* __restrict__ bias) {
    int gw = (blockIdx.x * blockDim.x + threadIdx.x) >> 5;
    int lane = threadIdx.x & 31;
    if (gw >= N_NODES) return;
    int node = gw;
    float di = g_dinv[node];
    const float4* hv = (const float4*)g_h1;
    float4 a = hv[node * 32 + lane];
    float w0 = di * di;
    float4 acc = make_float4(w0 * a.x, w0 * a.y, w0 * a.z, w0 * a.w);
    int e0 = g_rowptr[node], e1 = g_rowptr[node + 1];
    for (int e = e0; e < e1; e++) {
        int s = g_esrc[e];
        float w = di * g_dinv[s];
        float4 v = hv[s * 32 + lane];
        acc.x = fmaf(w, v.x, acc.x);
        acc.y = fmaf(w, v.y, acc.y);
        acc.z = fmaf(w, v.z, acc.z);
        acc.w = fmaf(w, v.w, acc.w);
    }
    float bx = bias[lane * 4 + 0], by = bias[lane * 4 + 1];
    float bz = bias[lane * 4 + 2], bw = bias[lane * 4 + 3];
    acc.x = fmaxf(acc.x + bx, 0.f);
    acc.y = fmaxf(acc.y + by, 0.f);
    acc.z = fmaxf(acc.z + bz, 0.f);
    acc.w = fmaxf(acc.w + bw, 0.f);
    ((float4*)g_a1)[node * 32 + lane] = acc;
}

// F=64 variant: float2 per lane, + bias, NO relu (final layer), writes d_out
__global__ void agg_bias_64_kernel(const float* __restrict__ bias,
                                   float* __restrict__ out) {
    int gw = (blockIdx.x * blockDim.x + threadIdx.x) >> 5;
    int lane = threadIdx.x & 31;
    if (gw >= N_NODES) return;
    int node = gw;
    float di = g_dinv[node];
    const float2* hv = (const float2*)g_h2;
    float2 a = hv[node * 32 + lane];
    float w0 = di * di;
    float2 acc = make_float2(w0 * a.x, w0 * a.y);
    int e0 = g_rowptr[node], e1 = g_rowptr[node + 1];
    for (int e = e0; e < e1; e++) {
        int s = g_esrc[e];
        float w = di * g_dinv[s];
        float2 v = hv[s * 32 + lane];
        acc.x = fmaf(w, v.x, acc.x);
        acc.y = fmaf(w, v.y, acc.y);
    }
    acc.x += bias[lane * 2 + 0];
    acc.y += bias[lane * 2 + 1];
    out[node * 64 + lane * 2 + 0] = acc.x;
    out[node * 64 + lane * 2 + 1] = acc.y;
}

// ---------------- launch ----------------------------------------------------
extern "C" void kernel_launch(void* const* d_in, const int* in_sizes, int n_in,
                              void* d_out, int out_size) {
    const float* x  = (const float*)d_in[0];
    const void*  ei = d_in[1];                 // int32 or int64 — sniffed on device
    const float* W1 = (const float*)d_in[2];
    const float* b1 = (const float*)d_in[3];
    const float* W2 = (const float*)d_in[4];
    const float* b2 = (const float*)d_in[5];
    float* out = (float*)d_out;

    // edge dtype detection + CSR-by-dst build (deterministic each call)
    detect_dtype_kernel<<<1, 32>>>(ei);
    zero_deg_kernel<<<(N_NODES + 255) / 256, 256>>>();
    count_deg_kernel<<<(N_EDGES + 255) / 256, 256>>>(ei);
    scan_local_kernel<<<SCAN_BLOCKS, 1024>>>();
    scan_sums_kernel<<<1, 64>>>();
    scan_finalize_kernel<<<(N_NODES + 255) / 256, 256>>>();
    fill_csr_kernel<<<(N_EDGES + 255) / 256, 256>>>(ei);

    // layer 1: h1 = x@W1 ; a1 = relu(agg(h1) + b1)
    gemm_tc_kernel<128, true><<<(N_NODES + 127) / 128, 256>>>(x, W1);
    agg_relu_bias_128_kernel<<<(N_NODES * 32 + 255) / 256, 256>>>(b1);

    // layer 2: h2 = a1@W2 ; out = agg(h2) + b2
    gemm_tc_kernel<64, false><<<(N_NODES + 127) / 128, 256>>>(nullptr, W2);
    agg_bias_64_kernel<<<(N_NODES * 32 + 255) / 256, 256>>>(b2, out);
}

// round 11
// speedup vs baseline: 2.6598x; 1.4855x over previous
#include <cuda_runtime.h>
#include <cuda_fp16.h>
#include <cstdint>

#define N_NODES 50000
#define N_EDGES 600000
#define F_MID 128
#define F_OUT 64
#define SCAN_BLOCKS ((N_NODES + 1023) / 1024)   // 49

// ---------------- scratch (static __device__, 256B-aligned) ----------------
__device__ __align__(256) __half g_h1h[N_NODES * F_MID]; // x @ W1   (fp16)
__device__ __align__(256) float  g_a1[N_NODES * F_MID];  // relu(agg1 + b1)
__device__ __align__(256) __half g_h2h[N_NODES * F_OUT]; // a1 @ W2  (fp16)
__device__ __align__(256) float  g_dinv[N_NODES];
__device__ __align__(256) int    g_deg[N_NODES];
__device__ __align__(256) int    g_rowptr[N_NODES + 1];
__device__ __align__(256) int    g_pos[N_NODES];
__device__ __align__(256) int    g_esrc[N_EDGES];
__device__ __align__(256) int    g_blocksum[64];
__device__ int g_is64;   // 1 if edge_index is int64, 0 if int32

__device__ __forceinline__ int load_edge(const void* ei, long long idx) {
    if (g_is64) return (int)((const long long*)ei)[idx];
    return ((const int*)ei)[idx];
}

// ---------------- CSR construction -----------------------------------------
// zero degrees + dtype sniff (int64 vals <50000 look like [v,0,...] int32 pairs)
__global__ void zero_detect_kernel(const void* __restrict__ ei) {
    int i = blockIdx.x * blockDim.x + threadIdx.x;
    if (i < N_NODES) g_deg[i] = 0;
    if (i == 0) {
        const int* p = (const int*)ei;
        int allz = 1;
        for (int k = 0; k < 128; k++)
            if (p[2 * k + 1] != 0) { allz = 0; break; }
        g_is64 = allz;
    }
}

__global__ void count_deg_kernel(const void* __restrict__ ei) {
    int e = blockIdx.x * blockDim.x + threadIdx.x;
    if (e < N_EDGES) {
        int d = load_edge(ei, (long long)N_EDGES + e);  // dst row
        if ((unsigned)d < (unsigned)N_NODES) atomicAdd(&g_deg[d], 1);
    }
}

// Phase 1: per-block (1024-wide) local exclusive scan + block totals
__global__ void scan_local_kernel() {
    __shared__ int warpsums[32];
    int tid = threadIdx.x, lane = tid & 31, wid = tid >> 5;
    int i = blockIdx.x * 1024 + tid;
    int v = (i < N_NODES) ? g_deg[i] : 0;
    int s = v;
    #pragma unroll
    for (int off = 1; off < 32; off <<= 1) {
        int t = __shfl_up_sync(0xffffffffu, s, off);
        if (lane >= off) s += t;
    }
    if (lane == 31) warpsums[wid] = s;
    __syncthreads();
    if (wid == 0) {
        int w = warpsums[lane];
        int sw = w;
        #pragma unroll
        for (int off = 1; off < 32; off <<= 1) {
            int t = __shfl_up_sync(0xffffffffu, sw, off);
            if (lane >= off) sw += t;
        }
        warpsums[lane] = sw - w;   // exclusive warp offsets
    }
    __syncthreads();
    int incl = s + warpsums[wid];
    if (i < N_NODES) g_rowptr[i] = incl - v;     // block-local exclusive
    if (tid == 1023) g_blocksum[blockIdx.x] = incl;
}

// Phase 2 (fused): every block scans the <=64 block sums in 2 warps, then
// finalizes rowptr and does prep (pos, dinv). Kills the 1-block sums kernel.
__global__ void scan_finalize_kernel() {
    __shared__ int s_off[64];
    __shared__ int s_w0tot;
    int t = threadIdx.x, lane = t & 31, wid = t >> 5;
    int v = 0, sIncl = 0;
    if (t < 64) {
        v = (t < SCAN_BLOCKS) ? g_blocksum[t] : 0;
        int s = v;
        #pragma unroll
        for (int off = 1; off < 32; off <<= 1) {
            int u = __shfl_up_sync(0xffffffffu, s, off);
            if (lane >= off) s += u;
        }
        if (wid == 0 && lane == 31) s_w0tot = s;
        sIncl = s;
    }
    __syncthreads();
    if (t < 64) {
        int incl = sIncl + (wid == 1 ? s_w0tot : 0);
        s_off[t] = incl - v;
        if (blockIdx.x == 0 && t == 63) g_rowptr[N_NODES] = incl;  // total
    }
    __syncthreads();
    int i = blockIdx.x * blockDim.x + t;
    if (i < N_NODES) {
        int r = g_rowptr[i] + s_off[i >> 10];
        g_rowptr[i] = r;
        g_pos[i] = r;
        g_dinv[i] = rsqrtf((float)(g_deg[i] + 1));  // +1 self-loop; always > 0
    }
}

__global__ void fill_csr_kernel(const void* __restrict__ ei) {
    int e = blockIdx.x * blockDim.x + threadIdx.x;
    if (e < N_EDGES) {
        int s = load_edge(ei, e);
        int d = load_edge(ei, (long long)N_EDGES + e);
        if ((unsigned)d < (unsigned)N_NODES && (unsigned)s < (unsigned)N_NODES) {
            int idx = atomicAdd(&g_pos[d], 1);
            g_esrc[idx] = s;
        }
    }
}

// ---------------- tf32 tensor-core GEMM, fp16 output -----------------------
// Chalf[M,BN] = A[M,128] * B[128,BN]. BM=128, BK=32, 256 thr = 8 warps 2x4.
__device__ __forceinline__ uint32_t f2tf32(float f) {
    uint32_t u;
    asm("cvt.rna.tf32.f32 %0, %1;" : "=r"(u) : "f"(f));
    return u;
}

template <int BN, bool LAYER1>
__global__ void gemm_tc_kernel(const float* __restrict__ Ain,
                               const float* __restrict__ B) {
    constexpr int BM = 128, BK = 32;
    constexpr int MT = 4;                 // 64 rows / 16
    constexpr int NT = (BN / 4) / 8;      // 4 (BN=128) or 2 (BN=64)
    constexpr int NAv = 4;                // A float4 loads/thread
    constexpr int NBv = BN / 32;          // B float4 loads/thread
    const int M = N_NODES;
    const float* A = LAYER1 ? Ain : (const float*)g_a1;
    __half* C = LAYER1 ? (__half*)g_h1h : (__half*)g_h2h;

    __shared__ float As[BM][BK + 4];      // +4 pad: conflict-free frag reads
    __shared__ float Bs[BK][BN + 4];

    int tid = threadIdx.x;
    int lane = tid & 31;
    int w = tid >> 5;
    int warp_m = w >> 2, warp_n = w & 3;
    int mrow0 = warp_m * 64;
    int ncol0 = warp_n * (BN / 4);
    int g = lane >> 2, q = lane & 3;
    int row0 = blockIdx.x * BM;

    float acc[MT][NT][4];
    #pragma unroll
    for (int i = 0; i < MT; i++)
        #pragma unroll
        for (int j = 0; j < NT; j++)
            #pragma unroll
            for (int k = 0; k < 4; k++) acc[i][j][k] = 0.f;

    float4 ra[NAv], rb[NBv];
    auto fetch = [&](int kb) {
        #pragma unroll
        for (int k = 0; k < NAv; k++) {
            int idx = tid + k * 256;
            int ar = idx >> 3, ac4 = idx & 7;
            int gr = row0 + ar;
            ra[k] = (gr < M) ? *(const float4*)&A[gr * 128 + kb + ac4 * 4]
                             : make_float4(0.f, 0.f, 0.f, 0.f);
        }
        #pragma unroll
        for (int k = 0; k < NBv; k++) {
            int idx = tid + k * 256;
            int br = idx / (BN / 4), bc4 = idx % (BN / 4);
            rb[k] = *(const float4*)&B[(kb + br) * BN + bc4 * 4];
        }
    };
    auto commit = [&]() {
        #pragma unroll
        for (int k = 0; k < NAv; k++) {
            int idx = tid + k * 256;
            int ar = idx >> 3, ac4 = idx & 7;
            *(float4*)&As[ar][ac4 * 4] = ra[k];
        }
        #pragma unroll
        for (int k = 0; k < NBv; k++) {
            int idx = tid + k * 256;
            int br = idx / (BN / 4), bc4 = idx % (BN / 4);
            *(float4*)&Bs[br][bc4 * 4] = rb[k];
        }
    };

    fetch(0);
    #pragma unroll
    for (int t = 0; t < 128 / BK; t++) {
        commit();
        __syncthreads();
        if (t < 128 / BK - 1) fetch((t + 1) * BK);   // next tile in flight
        #pragma unroll
        for (int ks = 0; ks < BK / 8; ks++) {
            int k0 = ks * 8;
            uint32_t af[MT][4];
            #pragma unroll
            for (int mt = 0; mt < MT; mt++) {
                int r = mrow0 + mt * 16 + g;
                af[mt][0] = f2tf32(As[r][k0 + q]);
                af[mt][1] = f2tf32(As[r + 8][k0 + q]);
                af[mt][2] = f2tf32(As[r][k0 + q + 4]);
                af[mt][3] = f2tf32(As[r + 8][k0 + q + 4]);
            }
            uint32_t bf[NT][2];
            #pragma unroll
            for (int nt = 0; nt < NT; nt++) {
                int c = ncol0 + nt * 8 + g;
                bf[nt][0] = f2tf32(Bs[k0 + q][c]);
                bf[nt][1] = f2tf32(Bs[k0 + q + 4][c]);
            }
            #pragma unroll
            for (int mt = 0; mt < MT; mt++)
                #pragma unroll
                for (int nt = 0; nt < NT; nt++) {
                    asm volatile(
                        "mma.sync.aligned.m16n8k8.row.col.f32.tf32.tf32.f32 "
                        "{%0,%1,%2,%3}, {%4,%5,%6,%7}, {%8,%9}, {%0,%1,%2,%3};"
                        : "+f"(acc[mt][nt][0]), "+f"(acc[mt][nt][1]),
                          "+f"(acc[mt][nt][2]), "+f"(acc[mt][nt][3])
                        : "r"(af[mt][0]), "r"(af[mt][1]),
                          "r"(af[mt][2]), "r"(af[mt][3]),
                          "r"(bf[nt][0]), "r"(bf[nt][1]));
                }
        }
        __syncthreads();
    }

    // epilogue: fp32 acc -> fp16 store. c0,c1 -> (g, 2q); c2,c3 -> (g+8, 2q)
    #pragma unroll
    for (int mt = 0; mt < MT; mt++) {
        int r = mrow0 + mt * 16 + g;
        int gr0 = row0 + r, gr1 = gr0 + 8;
        #pragma unroll
        for (int nt = 0; nt < NT; nt++) {
            int c = ncol0 + nt * 8 + 2 * q;
            if (gr0 < M)
                *(__half2*)&C[gr0 * BN + c] =
                    __floats2half2_rn(acc[mt][nt][0], acc[mt][nt][1]);
            if (gr1 < M)
                *(__half2*)&C[gr1 * BN + c] =
                    __floats2half2_rn(acc[mt][nt][2], acc[mt][nt][3]);
        }
    }
}

// ---------------- aggregation: warp-per-node gather (fp16 source) ----------
__device__ __forceinline__ float4 h4_to_f4(uint2 r) {
    __half2 a = *reinterpret_cast<__half2*>(&r.x);
    __half2 b = *reinterpret_cast<__half2*>(&r.y);
    float2 fa = __half22float2(a), fb = __half22float2(b);
    return make_float4(fa.x, fa.y, fb.x, fb.y);
}

// g_a1[i] = relu( dinv[i]^2*h1[i] + sum_e dinv[src]*dinv[i]*h1[src] + b1 )
__global__ void agg_relu_bias_128_kernel(const float* __restrict__ bias) {
    int gw = (blockIdx.x * blockDim.x + threadIdx.x) >> 5;
    int lane = threadIdx.x & 31;
    if (gw >= N_NODES) return;
    int node = gw;
    float di = g_dinv[node];
    const uint2* hv = (const uint2*)g_h1h;   // 4 halves per uint2; 32/row
    float4 a = h4_to_f4(hv[node * 32 + lane]);
    float w0 = di * di;
    float4 acc = make_float4(w0 * a.x, w0 * a.y, w0 * a.z, w0 * a.w);
    int e0 = g_rowptr[node], e1 = g_rowptr[node + 1];
    for (int e = e0; e < e1; e++) {
        int s = g_esrc[e];
        float w = di * g_dinv[s];
        float4 v = h4_to_f4(hv[s * 32 + lane]);
        acc.x = fmaf(w, v.x, acc.x);
        acc.y = fmaf(w, v.y, acc.y);
        acc.z = fmaf(w, v.z, acc.z);
        acc.w = fmaf(w, v.w, acc.w);
    }
    float bx = bias[lane * 4 + 0], by = bias[lane * 4 + 1];
    float bz = bias[lane * 4 + 2], bw = bias[lane * 4 + 3];
    acc.x = fmaxf(acc.x + bx, 0.f);
    acc.y = fmaxf(acc.y + by, 0.f);
    acc.z = fmaxf(acc.z + bz, 0.f);
    acc.w = fmaxf(acc.w + bw, 0.f);
    ((float4*)g_a1)[node * 32 + lane] = acc;
}

// F=64: 2 halves per lane, + bias, NO relu (final layer), writes fp32 d_out
__global__ void agg_bias_64_kernel(const float* __restrict__ bias,
                                   float* __restrict__ out) {
    int gw = (blockIdx.x * blockDim.x + threadIdx.x) >> 5;
    int lane = threadIdx.x & 31;
    if (gw >= N_NODES) return;
    int node = gw;
    float di = g_dinv[node];
    const uint32_t* hv = (const uint32_t*)g_h2h;  // 2 halves per u32; 32/row
    float2 a = __half22float2(*reinterpret_cast<const __half2*>(&hv[node * 32 + lane]));
    float w0 = di * di;
    float2 acc = make_float2(w0 * a.x, w0 * a.y);
    int e0 = g_rowptr[node], e1 = g_rowptr[node + 1];
    for (int e = e0; e < e1; e++) {
        int s = g_esrc[e];
        float w = di * g_dinv[s];
        uint32_t raw = hv[s * 32 + lane];
        float2 v = __half22float2(*reinterpret_cast<__half2*>(&raw));
        acc.x = fmaf(w, v.x, acc.x);
        acc.y = fmaf(w, v.y, acc.y);
    }
    acc.x += bias[lane * 2 + 0];
    acc.y += bias[lane * 2 + 1];
    out[node * 64 + lane * 2 + 0] = acc.x;
    out[node * 64 + lane * 2 + 1] = acc.y;
}

// ---------------- launch ----------------------------------------------------
extern "C" void kernel_launch(void* const* d_in, const int* in_sizes, int n_in,
                              void* d_out, int out_size) {
    const float* x  = (const float*)d_in[0];
    const void*  ei = d_in[1];                 // int32 or int64 — sniffed on device
    const float* W1 = (const float*)d_in[2];
    const float* b1 = (const float*)d_in[3];
    const float* W2 = (const float*)d_in[4];
    const float* b2 = (const float*)d_in[5];
    float* out = (float*)d_out;

    // CSR-by-dst build (deterministic each call)
    zero_detect_kernel<<<(N_NODES + 255) / 256, 256>>>(ei);
    count_deg_kernel<<<(N_EDGES + 255) / 256, 256>>>(ei);
    scan_local_kernel<<<SCAN_BLOCKS, 1024>>>();
    scan_finalize_kernel<<<(N_NODES + 255) / 256, 256>>>();
    fill_csr_kernel<<<(N_EDGES + 255) / 256, 256>>>(ei);

    // layer 1: h1 = x@W1 (fp16) ; a1 = relu(agg(h1) + b1) (fp32)
    gemm_tc_kernel<128, true><<<(N_NODES + 127) / 128, 256>>>(x, W1);
    agg_relu_bias_128_kernel<<<(N_NODES * 32 + 255) / 256, 256>>>(b1);

    // layer 2: h2 = a1@W2 (fp16) ; out = agg(h2) + b2 (fp32)
    gemm_tc_kernel<64, false><<<(N_NODES + 127) / 128, 256>>>(nullptr, W2);
    agg_bias_64_kernel<<<(N_NODES * 32 + 255) / 256, 256>>>(b2, out);
}